// round 1
// baseline (speedup 1.0000x reference)
#include <cuda_runtime.h>
#include <math.h>

#define N_NODES 50000
#define N_EDGES 400000
#define TTAB    8192

// ---------------- device scratch (static allocation, allowed) ----------------
__device__ float g_agg_s[N_NODES * 64];          // 12.8 MB
__device__ float g_agg_v[N_NODES * 192];         // 38.4 MB
__device__ float g_cnt[N_NODES];                 // 0.2 MB
__device__ float g_tab[(TTAB + 1) * 128];        // 4.2 MB  MLP lookup table
__device__ float g_act[N_NODES * 128];           // 25.6 MB act_s
__device__ float g_gate[N_NODES * 64];           // 12.8 MB gates
__device__ float g_gv[N_NODES * 192];            // 38.4 MB gated vectors

__device__ __forceinline__ float siluf(float x) { return x / (1.0f + expf(-x)); }
__device__ __forceinline__ float sigmf(float x) { return 1.0f / (1.0f + expf(-x)); }

// ---------------- zero the accumulators ----------------
__global__ void zero_kernel() {
    long idx = (long)blockIdx.x * blockDim.x + threadIdx.x;
    long stride = (long)gridDim.x * blockDim.x;
    float4 z = make_float4(0.f, 0.f, 0.f, 0.f);
    float4* a = (float4*)g_agg_s;
    for (long i = idx; i < N_NODES * 64 / 4; i += stride) a[i] = z;
    float4* b = (float4*)g_agg_v;
    for (long i = idx; i < N_NODES * 192 / 4; i += stride) b[i] = z;
    float4* c = (float4*)g_cnt;
    for (long i = idx; i < N_NODES / 4; i += stride) c[i] = z;
}

// ---------------- build MLP lookup table: scal = f(norm), norm in [0,1] ------
// grid = TTAB+1 blocks, 64 threads. Block i evaluates the full MLP at x=i/TTAB.
__global__ void table_kernel(const float* __restrict__ w1, const float* __restrict__ b1,
                             const float* __restrict__ w2, const float* __restrict__ b2,
                             const float* __restrict__ w3, const float* __restrict__ b3) {
    __shared__ float h1[64];
    __shared__ float h2[64];
    int i = blockIdx.x;
    int j = threadIdx.x;
    float x = (float)i / (float)TTAB;
    h1[j] = siluf(x * w1[j] + b1[j]);
    __syncthreads();
    float acc = b2[j];
#pragma unroll 8
    for (int k = 0; k < 64; k++) acc += h1[k] * w2[k * 64 + j];
    h2[j] = siluf(acc);
    __syncthreads();
    float a0 = b3[j], a1 = b3[64 + j];
#pragma unroll 8
    for (int k = 0; k < 64; k++) {
        float h = h2[k];
        a0 += h * w3[k * 128 + j];
        a1 += h * w3[k * 128 + 64 + j];
    }
    g_tab[i * 128 + j]      = a0;
    g_tab[i * 128 + 64 + j] = a1;
}

// ---------------- edge kernel: one warp per edge, lane = mul index m ---------
__global__ __launch_bounds__(256) void edge_kernel(
    const float* __restrict__ node_scalars, const float* __restrict__ node_vectors,
    const float* __restrict__ sh, const float* __restrict__ nrm,
    const int* __restrict__ snd, const int* __restrict__ rcv) {
    int gwarp = (blockIdx.x * blockDim.x + threadIdx.x) >> 5;
    int lane = threadIdx.x & 31;
    if (gwarp >= N_EDGES) return;
    int e = gwarp;
    int s = snd[e];
    int r = rcv[e];
    float y0  = sh[e * 4 + 0];
    float y1x = sh[e * 4 + 1];
    float y1y = sh[e * 4 + 2];
    float y1z = sh[e * 4 + 3];

    // table interpolation of the 128-dim scale vector
    float u = nrm[e] * (float)TTAB;
    u = fminf(fmaxf(u, 0.0f), (float)TTAB);
    int i0 = min((int)u, TTAB - 1);
    float f = u - (float)i0;
    const float* t0 = g_tab + i0 * 128;

    float sA = t0[lane];        sA += f * (t0[128 + lane]        - sA);
    float sB = t0[32 + lane];   sB += f * (t0[128 + 32 + lane]   - sB);
    float sC = t0[64 + lane];   sC += f * (t0[128 + 64 + lane]   - sC);
    float sD = t0[96 + lane];   sD += f * (t0[128 + 96 + lane]   - sD);

    float se = node_scalars[s * 32 + lane];
    float vx = node_vectors[s * 96 + lane * 3 + 0];
    float vy = node_vectors[s * 96 + lane * 3 + 1];
    float vz = node_vectors[s * 96 + lane * 3 + 2];

    const float RS3 = 0.57735026919f;  // 1/sqrt(3)
    float tps0 = y0 * se * sA;
    float dotv = y1x * vx + y1y * vy + y1z * vz;
    float tps1 = dotv * RS3 * sB;

    atomicAdd(&g_agg_s[r * 64 + lane],      tps0);
    atomicAdd(&g_agg_s[r * 64 + 32 + lane], tps1);

    float c0 = y0 * sC;
    atomicAdd(&g_agg_v[r * 192 + lane * 3 + 0], c0 * vx);
    atomicAdd(&g_agg_v[r * 192 + lane * 3 + 1], c0 * vy);
    atomicAdd(&g_agg_v[r * 192 + lane * 3 + 2], c0 * vz);
    float d0 = se * sD;
    atomicAdd(&g_agg_v[r * 192 + 96 + lane * 3 + 0], d0 * y1x);
    atomicAdd(&g_agg_v[r * 192 + 96 + lane * 3 + 1], d0 * y1y);
    atomicAdd(&g_agg_v[r * 192 + 96 + lane * 3 + 2], d0 * y1z);
    if (lane == 0) atomicAdd(&g_cnt[r], 1.0f);
}

// ---------------- N1: x_s = (agg_s/denom)@lin1_w_s/8 -> act (128) + gates (64)
// block = 192 threads, 16 nodes/block. thread: x=tid%48 (4 output cols), 4 nodes.
__global__ __launch_bounds__(192) void n1_kernel(const float* __restrict__ W) {
    __shared__ float sa[16][64];
    __shared__ float sinv[16];
    int nbase = blockIdx.x * 16;
    int tid = threadIdx.x;
    if (tid < 16) sinv[tid] = 0.125f / fmaxf(g_cnt[nbase + tid], 1.0f);
    __syncthreads();
    for (int idx = tid; idx < 16 * 64; idx += 192) {
        int nn = idx >> 6, k = idx & 63;
        sa[nn][k] = g_agg_s[(nbase + nn) * 64 + k] * sinv[nn];
    }
    __syncthreads();
    int x = tid % 48, y = tid / 48;
    float4 acc[4];
#pragma unroll
    for (int nn = 0; nn < 4; nn++) acc[nn] = make_float4(0.f, 0.f, 0.f, 0.f);
    const float4* W4 = (const float4*)W;
#pragma unroll 4
    for (int k = 0; k < 64; k++) {
        float4 w = W4[k * 48 + x];
#pragma unroll
        for (int nn = 0; nn < 4; nn++) {
            float a = sa[y * 4 + nn][k];
            acc[nn].x += a * w.x; acc[nn].y += a * w.y;
            acc[nn].z += a * w.z; acc[nn].w += a * w.w;
        }
    }
    int j = x * 4;
#pragma unroll
    for (int nn = 0; nn < 4; nn++) {
        int n = nbase + y * 4 + nn;
        float4 v = acc[nn];
        if (j < 128) {
            v.x = siluf(v.x); v.y = siluf(v.y); v.z = siluf(v.z); v.w = siluf(v.w);
            *(float4*)&g_act[n * 128 + j] = v;
        } else {
            v.x = sigmf(v.x); v.y = sigmf(v.y); v.z = sigmf(v.z); v.w = sigmf(v.w);
            *(float4*)&g_gate[n * 64 + (j - 128)] = v;
        }
    }
}

// ---------------- N2: g_v = gates * ((agg_v/denom)@lin1_w_v/8) ---------------
// block = 192 threads, 16 nodes/block. x=tid%48: i=x/16 (xyz), mg=x%16 (4 m-cols)
__global__ __launch_bounds__(192) void n2_kernel(const float* __restrict__ Wv) {
    __shared__ float sv[16][192];
    __shared__ float sinv[16];
    int nbase = blockIdx.x * 16;
    int tid = threadIdx.x;
    if (tid < 16) sinv[tid] = 0.125f / fmaxf(g_cnt[nbase + tid], 1.0f);
    __syncthreads();
    for (int idx = tid; idx < 16 * 192; idx += 192) {
        int nn = idx / 192, q = idx % 192;
        sv[nn][q] = g_agg_v[(nbase + nn) * 192 + q] * sinv[nn];
    }
    __syncthreads();
    int x = tid % 48, y = tid / 48;
    int i = x / 16, mg = x % 16;
    const float4* W4 = (const float4*)Wv;
    float4 acc[4];
#pragma unroll
    for (int nn = 0; nn < 4; nn++) acc[nn] = make_float4(0.f, 0.f, 0.f, 0.f);
#pragma unroll 4
    for (int k = 0; k < 64; k++) {
        float4 w = W4[k * 16 + mg];
#pragma unroll
        for (int nn = 0; nn < 4; nn++) {
            float a = sv[y * 4 + nn][k * 3 + i];
            acc[nn].x += a * w.x; acc[nn].y += a * w.y;
            acc[nn].z += a * w.z; acc[nn].w += a * w.w;
        }
    }
#pragma unroll
    for (int nn = 0; nn < 4; nn++) {
        int n = nbase + y * 4 + nn;
        float4 g = *(const float4*)&g_gate[n * 64 + mg * 4];
        float* dst = &g_gv[n * 192];
        dst[(mg * 4 + 0) * 3 + i] = acc[nn].x * g.x;
        dst[(mg * 4 + 1) * 3 + i] = acc[nn].y * g.y;
        dst[(mg * 4 + 2) * 3 + i] = acc[nn].z * g.z;
        dst[(mg * 4 + 3) * 3 + i] = acc[nn].w * g.w;
    }
}

// ---------------- N3: final linear layers -> d_out ---------------------------
// block = 128 threads, 16 nodes/block.
//   warp 0 (tid<32): o_s (160 -> 32), og=tid&7, slot=tid>>3
//   warps 1-3:       o_v (96 -> 32 per xyz), og=t&7, i=(t>>3)%3, slot=t/24
__global__ __launch_bounds__(128) void n3_kernel(
    const float* __restrict__ Ws, const float* __restrict__ Wv,
    const float* __restrict__ node_scalars, const float* __restrict__ node_vectors,
    float* __restrict__ out) {
    __shared__ float cs[16][160];
    __shared__ float cv[16][288];
    int nbase = blockIdx.x * 16;
    int tid = threadIdx.x;
    const float s160 = 0.07905694150420949f;  // 1/sqrt(160)
    const float s96  = 0.10206207261596577f;  // 1/sqrt(96)
    for (int idx = tid; idx < 16 * 160; idx += 128) {
        int nn = idx / 160, c = idx % 160;
        int n = nbase + nn;
        float v = (c < 128) ? g_act[n * 128 + c] : node_scalars[n * 32 + (c - 128)];
        cs[nn][c] = v * s160;
    }
    for (int idx = tid; idx < 16 * 288; idx += 128) {
        int nn = idx / 288, q = idx % 288;
        int n = nbase + nn;
        int m = q / 3, i = q % 3;
        float v = (m < 64) ? g_gv[n * 192 + q] : node_vectors[n * 96 + (m - 64) * 3 + i];
        cv[nn][q] = v * s96;
    }
    __syncthreads();

    if (tid < 32) {
        int og = tid & 7, slot = tid >> 3;
        const float4* Ws4 = (const float4*)Ws;
        float4 acc[4];
#pragma unroll
        for (int nn = 0; nn < 4; nn++) acc[nn] = make_float4(0.f, 0.f, 0.f, 0.f);
#pragma unroll 4
        for (int c = 0; c < 160; c++) {
            float4 w = Ws4[c * 8 + og];
#pragma unroll
            for (int nn = 0; nn < 4; nn++) {
                float a = cs[slot * 4 + nn][c];
                acc[nn].x += a * w.x; acc[nn].y += a * w.y;
                acc[nn].z += a * w.z; acc[nn].w += a * w.w;
            }
        }
#pragma unroll
        for (int nn = 0; nn < 4; nn++) {
            int n = nbase + slot * 4 + nn;
            *(float4*)&out[n * 128 + og * 4] = acc[nn];
        }
    } else {
        int t = tid - 32;
        int og = t & 7;
        int i = (t >> 3) % 3;
        int slot = t / 24;
        const float4* Wv4 = (const float4*)Wv;
        float4 acc[4];
#pragma unroll
        for (int nn = 0; nn < 4; nn++) acc[nn] = make_float4(0.f, 0.f, 0.f, 0.f);
#pragma unroll 4
        for (int m = 0; m < 96; m++) {
            float4 w = Wv4[m * 8 + og];
#pragma unroll
            for (int nn = 0; nn < 4; nn++) {
                float a = cv[slot * 4 + nn][m * 3 + i];
                acc[nn].x += a * w.x; acc[nn].y += a * w.y;
                acc[nn].z += a * w.z; acc[nn].w += a * w.w;
            }
        }
#pragma unroll
        for (int nn = 0; nn < 4; nn++) {
            int n = nbase + slot * 4 + nn;
            float* dst = &out[n * 128 + 32];
            dst[(og * 4 + 0) * 3 + i] = acc[nn].x;
            dst[(og * 4 + 1) * 3 + i] = acc[nn].y;
            dst[(og * 4 + 2) * 3 + i] = acc[nn].z;
            dst[(og * 4 + 3) * 3 + i] = acc[nn].w;
        }
    }
}

// ---------------- launch ----------------
extern "C" void kernel_launch(void* const* d_in, const int* in_sizes, int n_in,
                              void* d_out, int out_size) {
    const float* node_scalars = (const float*)d_in[0];
    const float* node_vectors = (const float*)d_in[1];
    const float* sh           = (const float*)d_in[2];
    const float* nrm          = (const float*)d_in[3];
    const float* w1           = (const float*)d_in[4];
    const float* b1           = (const float*)d_in[5];
    const float* w2           = (const float*)d_in[6];
    const float* b2           = (const float*)d_in[7];
    const float* w3           = (const float*)d_in[8];
    const float* b3           = (const float*)d_in[9];
    const float* l1s          = (const float*)d_in[10];
    const float* l1v          = (const float*)d_in[11];
    const float* l2s          = (const float*)d_in[12];
    const float* l2v          = (const float*)d_in[13];
    const int*   snd          = (const int*)d_in[14];
    const int*   rcv          = (const int*)d_in[15];
    float* out = (float*)d_out;

    zero_kernel<<<2048, 256>>>();
    table_kernel<<<TTAB + 1, 64>>>(w1, b1, w2, b2, w3, b3);
    edge_kernel<<<N_EDGES / 8, 256>>>(node_scalars, node_vectors, sh, nrm, snd, rcv);
    n1_kernel<<<N_NODES / 16, 192>>>(l1s);
    n2_kernel<<<N_NODES / 16, 192>>>(l1v);
    n3_kernel<<<N_NODES / 16, 128>>>(l2s, l2v, node_scalars, node_vectors, out);
}